// round 7
// baseline (speedup 1.0000x reference)
#include <cuda_runtime.h>
#include <cuda_bf16.h>

#define N_GRID 64
#define N1 65
#define W_FEAT 256
#define NCELLS (N_GRID * N_GRID * N_GRID)   // 262144
#define B_MAX 262144

// Scratch (allocation-free rule: __device__ globals).
// g_hist must be zero at first use: static zero-init gives that, and
// scan_block_kernel resets it each pass so graph replays stay correct.
__device__ int g_hist[NCELLS];        // zero-initialized
__device__ int g_offsets[NCELLS];     // exclusive prefix within 1024-chunk
__device__ int g_blocksums[256];
__device__ int g_cell[B_MAX];
__device__ int g_perm[B_MAX];

__global__ void hist_kernel(const float* __restrict__ x, int B) {
    int p = blockIdx.x * blockDim.x + threadIdx.x;
    if (p >= B) return;
    const float scale = (float)N_GRID / 2.0f;
    float rx = (x[p * 3 + 0] + 1.0f) * scale;
    float ry = (x[p * 3 + 1] + 1.0f) * scale;
    float rz = (x[p * 3 + 2] + 1.0f) * scale;
    int ix = min(max((int)floorf(rx), 0), N_GRID - 1);
    int iy = min(max((int)floorf(ry), 0), N_GRID - 1);
    int iz = min(max((int)floorf(rz), 0), N_GRID - 1);
    int cell = (ix * N_GRID + iy) * N_GRID + iz;   // lexicographic = memory order
    g_cell[p] = cell;
    atomicAdd(&g_hist[cell], 1);
}

// 256 blocks x 1024 threads. Per-chunk exclusive scan into g_offsets,
// reset g_hist to 0, emit chunk total.
__global__ void __launch_bounds__(1024) scan_block_kernel() {
    __shared__ int s[1024];
    int tid = threadIdx.x;
    int i = blockIdx.x * 1024 + tid;
    int v = g_hist[i];
    s[tid] = v;
    __syncthreads();
    #pragma unroll
    for (int off = 1; off < 1024; off <<= 1) {
        int t = (tid >= off) ? s[tid - off] : 0;
        __syncthreads();
        s[tid] += t;
        __syncthreads();
    }
    g_offsets[i] = s[tid] - v;        // exclusive within chunk
    g_hist[i] = 0;                    // ready for next replay
    if (tid == 1023) g_blocksums[blockIdx.x] = s[1023];
}

// 1 block x 256 threads: exclusive scan of chunk sums in place.
__global__ void scan_top_kernel() {
    __shared__ int s[256];
    int tid = threadIdx.x;
    int v = g_blocksums[tid];
    s[tid] = v;
    __syncthreads();
    #pragma unroll
    for (int off = 1; off < 256; off <<= 1) {
        int t = (tid >= off) ? s[tid - off] : 0;
        __syncthreads();
        s[tid] += t;
        __syncthreads();
    }
    g_blocksums[tid] = s[tid] - v;
}

__global__ void scatter_kernel(int B) {
    int p = blockIdx.x * blockDim.x + threadIdx.x;
    if (p >= B) return;
    int c = g_cell[p];
    int pos = atomicAdd(&g_offsets[c], 1) + g_blocksums[c >> 10];
    g_perm[pos] = p;
}

// warp-per-point trilinear gather; warps walk points in cell-sorted order.
// All 16 feature loads issued before any FMA -> MLP=16 per warp.
// launch_bounds(256, 3): 85-reg cap, ~24 warps/SM -> ~380 loads in flight/SM.
__global__ void __launch_bounds__(256, 3) trilerp_kernel(
    const float* __restrict__ x,
    const float* __restrict__ grid_value,
    const float* __restrict__ grid_feature,
    float* __restrict__ out_val,
    float* __restrict__ out_feat,
    int B)
{
    int warp_id = (blockIdx.x * blockDim.x + threadIdx.x) >> 5;
    int lane = threadIdx.x & 31;
    if (warp_id >= B) return;

    int p = g_perm[warp_id];

    float px = x[p * 3 + 0];
    float py = x[p * 3 + 1];
    float pz = x[p * 3 + 2];

    const float scale = (float)N_GRID / 2.0f;
    float rx = (px + 1.0f) * scale;
    float ry = (py + 1.0f) * scale;
    float rz = (pz + 1.0f) * scale;

    bool valid = (rx >= 0.0f) && (rx <= (float)N_GRID) &&
                 (ry >= 0.0f) && (ry <= (float)N_GRID) &&
                 (rz >= 0.0f) && (rz <= (float)N_GRID);

    int ix = min(max((int)floorf(rx), 0), N_GRID - 1);
    int iy = min(max((int)floorf(ry), 0), N_GRID - 1);
    int iz = min(max((int)floorf(rz), 0), N_GRID - 1);

    float tx = rx - (float)ix;
    float ty = ry - (float)iy;
    float tz = rz - (float)iz;

    int base = (ix * N1 + iy) * N1 + iz;

    float wx0 = 1.0f - tx, wx1 = tx;
    float wy0 = 1.0f - ty, wy1 = ty;
    float wz0 = 1.0f - tz, wz1 = tz;

    float w[8];
    w[0] = wx0 * wy0 * wz0;
    w[1] = wx0 * wy0 * wz1;
    w[2] = wx0 * wy1 * wz0;
    w[3] = wx0 * wy1 * wz1;
    w[4] = wx1 * wy0 * wz0;
    w[5] = wx1 * wy0 * wz1;
    w[6] = wx1 * wy1 * wz0;
    w[7] = wx1 * wy1 * wz1;

    const float4* bp = (const float4*)(grid_feature + (size_t)base * W_FEAT) + lane;

    // Phase 1: issue ALL 16 loads (corner offsets are compile-time imms).
    float4 f[16];
    #pragma unroll
    for (int c = 0; c < 8; c++) {
        int off = (((c >> 2) & 1) * (N1 * N1) + ((c >> 1) & 1) * N1 + (c & 1)) * (W_FEAT / 4);
        f[c * 2 + 0] = __ldg(bp + off);
        f[c * 2 + 1] = __ldg(bp + off + 32);
    }

    // Phase 2: all FMAs.
    float4 acc0 = make_float4(0.f, 0.f, 0.f, 0.f);
    float4 acc1 = make_float4(0.f, 0.f, 0.f, 0.f);
    #pragma unroll
    for (int c = 0; c < 8; c++) {
        float wc = w[c];
        acc0.x += wc * f[c * 2].x; acc0.y += wc * f[c * 2].y;
        acc0.z += wc * f[c * 2].z; acc0.w += wc * f[c * 2].w;
        acc1.x += wc * f[c * 2 + 1].x; acc1.y += wc * f[c * 2 + 1].y;
        acc1.z += wc * f[c * 2 + 1].z; acc1.w += wc * f[c * 2 + 1].w;
    }

    if (!valid) {
        acc0 = make_float4(0.f, 0.f, 0.f, 0.f);
        acc1 = make_float4(0.f, 0.f, 0.f, 0.f);
    }

    float4* fo = (float4*)(out_feat + (size_t)p * W_FEAT);
    fo[lane]      = acc0;
    fo[lane + 32] = acc1;

    if (lane == 0) {
        float s = 0.0f;
        #pragma unroll
        for (int c = 0; c < 8; c++) {
            int off = ((c >> 2) & 1) * (N1 * N1) + ((c >> 1) & 1) * N1 + (c & 1);
            s += w[c] * __ldg(&grid_value[base + off]);
        }
        out_val[p] = valid ? s : 0.0f;
    }
}

extern "C" void kernel_launch(void* const* d_in, const int* in_sizes, int n_in,
                              void* d_out, int out_size) {
    const float* x            = (const float*)d_in[0];
    const float* grid_value   = (const float*)d_in[1];
    const float* grid_feature = (const float*)d_in[2];

    int B = in_sizes[0] / 3;

    float* out_val  = (float*)d_out;        // (B, 1)
    float* out_feat = out_val + B;          // (B, 256)

    // --- counting sort by full cell id (lean 4-kernel pipeline) ---
    hist_kernel<<<(B + 255) / 256, 256>>>(x, B);
    scan_block_kernel<<<NCELLS / 1024, 1024>>>();
    scan_top_kernel<<<1, 256>>>();
    scatter_kernel<<<(B + 255) / 256, 256>>>(B);

    // --- main gather: warp per point, sorted order ---
    int warps_per_block = 8;                 // 256 threads
    int blocks = (B + warps_per_block - 1) / warps_per_block;
    trilerp_kernel<<<blocks, 256>>>(x, grid_value, grid_feature,
                                    out_val, out_feat, B);
}

// round 8
// speedup vs baseline: 1.2894x; 1.2894x over previous
#include <cuda_runtime.h>
#include <cuda_bf16.h>

#define N_GRID 64
#define N1 65
#define W_FEAT 256
#define NCELLS (N_GRID * N_GRID * N_GRID)   // 262144
#define B_MAX 262144

// Scratch (allocation-free rule: __device__ globals).
// g_hist must be zero at first use: static zero-init gives that, and
// scan_block_kernel resets it each pass so graph replays stay correct.
__device__ int    g_hist[NCELLS];      // zero-initialized
__device__ int    g_offsets[NCELLS];   // exclusive prefix within 1024-chunk
__device__ int    g_blocksums[256];    // RAW chunk totals (scanned inline in scatter)
__device__ int    g_cell[B_MAX];
__device__ float4 g_pts[B_MAX];        // sorted payload: (x, y, z, bitcast(point id))

__global__ void hist_kernel(const float* __restrict__ x, int B) {
    int p = blockIdx.x * blockDim.x + threadIdx.x;
    if (p >= B) return;
    const float scale = (float)N_GRID / 2.0f;
    float rx = (x[p * 3 + 0] + 1.0f) * scale;
    float ry = (x[p * 3 + 1] + 1.0f) * scale;
    float rz = (x[p * 3 + 2] + 1.0f) * scale;
    int ix = min(max((int)floorf(rx), 0), N_GRID - 1);
    int iy = min(max((int)floorf(ry), 0), N_GRID - 1);
    int iz = min(max((int)floorf(rz), 0), N_GRID - 1);
    int cell = (ix * N_GRID + iy) * N_GRID + iz;   // lexicographic = memory order
    g_cell[p] = cell;
    atomicAdd(&g_hist[cell], 1);
}

// 256 blocks x 1024 threads: shuffle-based exclusive scan of each 1024-chunk
// into g_offsets, reset g_hist, emit RAW chunk total.
__global__ void __launch_bounds__(1024) scan_block_kernel() {
    __shared__ int wsum[32];
    int tid = threadIdx.x;
    int lane = tid & 31;
    int wid = tid >> 5;
    int i = blockIdx.x * 1024 + tid;

    int v = g_hist[i];
    int inc = v;
    #pragma unroll
    for (int off = 1; off < 32; off <<= 1) {
        int t = __shfl_up_sync(0xFFFFFFFF, inc, off);
        if (lane >= off) inc += t;
    }
    if (lane == 31) wsum[wid] = inc;
    __syncthreads();
    if (wid == 0) {
        int ws = wsum[lane];
        int winc = ws;
        #pragma unroll
        for (int off = 1; off < 32; off <<= 1) {
            int t = __shfl_up_sync(0xFFFFFFFF, winc, off);
            if (lane >= off) winc += t;
        }
        wsum[lane] = winc - ws;      // exclusive warp prefix
    }
    __syncthreads();
    int excl = inc - v + wsum[wid];
    g_offsets[i] = excl;
    g_hist[i] = 0;                   // ready for next replay
    if (tid == 1023) g_blocksums[blockIdx.x] = excl + v;  // raw chunk total
}

// 1024 blocks x 256 threads. Each block first scans the 256 raw chunk totals
// in smem (replaces the scan_top kernel), then scatters 256 points as float4
// payloads into sorted order.
__global__ void __launch_bounds__(256) scatter_kernel(const float* __restrict__ x, int B) {
    __shared__ int bs[256];
    __shared__ int wsum[8];
    int tid = threadIdx.x;
    int lane = tid & 31;
    int wid = tid >> 5;

    int raw = g_blocksums[tid];
    int inc = raw;
    #pragma unroll
    for (int off = 1; off < 32; off <<= 1) {
        int t = __shfl_up_sync(0xFFFFFFFF, inc, off);
        if (lane >= off) inc += t;
    }
    if (lane == 31) wsum[wid] = inc;
    __syncthreads();
    if (wid == 0 && lane < 8) {
        int ws = wsum[lane];
        int winc = ws;
        #pragma unroll
        for (int off = 1; off < 8; off <<= 1) {
            int t = __shfl_up_sync(0x000000FF, winc, off);
            if (lane >= off) winc += t;
        }
        wsum[lane] = winc - ws;      // exclusive warp prefix
    }
    __syncthreads();
    bs[tid] = inc - raw + wsum[wid]; // exclusive prefix of chunk totals
    __syncthreads();

    int p = blockIdx.x * 256 + tid;
    if (p >= B) return;
    int c = g_cell[p];
    int pos = atomicAdd(&g_offsets[c], 1) + bs[c >> 10];
    g_pts[pos] = make_float4(x[p * 3 + 0], x[p * 3 + 1], x[p * 3 + 2],
                             __int_as_float(p));
}

// warp-per-point trilinear gather; warps walk points in cell-sorted order.
// (R6-measured-best loop structure: interleaved load/FMA, 44 regs.)
__global__ void __launch_bounds__(256) trilerp_kernel(
    const float* __restrict__ grid_value,
    const float* __restrict__ grid_feature,
    float* __restrict__ out_val,
    float* __restrict__ out_feat,
    int B)
{
    int warp_id = (blockIdx.x * blockDim.x + threadIdx.x) >> 5;
    int lane = threadIdx.x & 31;
    if (warp_id >= B) return;

    float4 pt = __ldg(&g_pts[warp_id]);   // broadcast: coords + point id
    float px = pt.x, py = pt.y, pz = pt.z;
    int p = __float_as_int(pt.w);

    const float scale = (float)N_GRID / 2.0f;
    float rx = (px + 1.0f) * scale;
    float ry = (py + 1.0f) * scale;
    float rz = (pz + 1.0f) * scale;

    bool valid = (rx >= 0.0f) && (rx <= (float)N_GRID) &&
                 (ry >= 0.0f) && (ry <= (float)N_GRID) &&
                 (rz >= 0.0f) && (rz <= (float)N_GRID);

    int ix = min(max((int)floorf(rx), 0), N_GRID - 1);
    int iy = min(max((int)floorf(ry), 0), N_GRID - 1);
    int iz = min(max((int)floorf(rz), 0), N_GRID - 1);

    float tx = rx - (float)ix;
    float ty = ry - (float)iy;
    float tz = rz - (float)iz;

    int base = (ix * N1 + iy) * N1 + iz;

    float wx0 = 1.0f - tx, wx1 = tx;
    float wy0 = 1.0f - ty, wy1 = ty;
    float wz0 = 1.0f - tz, wz1 = tz;

    int   flat[8];
    float w[8];
    flat[0] = base;                      w[0] = wx0 * wy0 * wz0;
    flat[1] = base + 1;                  w[1] = wx0 * wy0 * wz1;
    flat[2] = base + N1;                 w[2] = wx0 * wy1 * wz0;
    flat[3] = base + N1 + 1;             w[3] = wx0 * wy1 * wz1;
    flat[4] = base + N1 * N1;            w[4] = wx1 * wy0 * wz0;
    flat[5] = base + N1 * N1 + 1;        w[5] = wx1 * wy0 * wz1;
    flat[6] = base + N1 * N1 + N1;       w[6] = wx1 * wy1 * wz0;
    flat[7] = base + N1 * N1 + N1 + 1;   w[7] = wx1 * wy1 * wz1;

    float4 acc0 = make_float4(0.f, 0.f, 0.f, 0.f);
    float4 acc1 = make_float4(0.f, 0.f, 0.f, 0.f);

    #pragma unroll
    for (int c = 0; c < 8; c++) {
        const float4* row = (const float4*)(grid_feature + (size_t)flat[c] * W_FEAT);
        float4 f0 = __ldg(&row[lane]);
        float4 f1 = __ldg(&row[lane + 32]);
        float wc = w[c];
        acc0.x += wc * f0.x; acc0.y += wc * f0.y;
        acc0.z += wc * f0.z; acc0.w += wc * f0.w;
        acc1.x += wc * f1.x; acc1.y += wc * f1.y;
        acc1.z += wc * f1.z; acc1.w += wc * f1.w;
    }

    if (!valid) {
        acc0 = make_float4(0.f, 0.f, 0.f, 0.f);
        acc1 = make_float4(0.f, 0.f, 0.f, 0.f);
    }

    float4* fo = (float4*)(out_feat + (size_t)p * W_FEAT);
    fo[lane]      = acc0;
    fo[lane + 32] = acc1;

    if (lane == 0) {
        float s = 0.0f;
        #pragma unroll
        for (int c = 0; c < 8; c++) s += w[c] * __ldg(&grid_value[flat[c]]);
        out_val[p] = valid ? s : 0.0f;
    }
}

extern "C" void kernel_launch(void* const* d_in, const int* in_sizes, int n_in,
                              void* d_out, int out_size) {
    const float* x            = (const float*)d_in[0];
    const float* grid_value   = (const float*)d_in[1];
    const float* grid_feature = (const float*)d_in[2];

    int B = in_sizes[0] / 3;

    float* out_val  = (float*)d_out;        // (B, 1)
    float* out_feat = out_val + B;          // (B, 256)

    // --- counting sort by full cell id (4 launches total incl. main) ---
    hist_kernel<<<(B + 255) / 256, 256>>>(x, B);
    scan_block_kernel<<<NCELLS / 1024, 1024>>>();
    scatter_kernel<<<(B + 255) / 256, 256>>>(x, B);

    // --- main gather: warp per point, sorted order ---
    int warps_per_block = 8;                 // 256 threads
    int blocks = (B + warps_per_block - 1) / warps_per_block;
    trilerp_kernel<<<blocks, 256>>>(grid_value, grid_feature,
                                    out_val, out_feat, B);
}

// round 9
// speedup vs baseline: 1.3136x; 1.0187x over previous
#include <cuda_runtime.h>
#include <cuda_bf16.h>

#define N_GRID 64
#define N1 65
#define W_FEAT 256
#define NCELLS (N_GRID * N_GRID * N_GRID)   // 262144
#define B_MAX 262144

// Scratch (allocation-free rule: __device__ globals).
// g_hist must be zero at first use: static zero-init gives that, and
// scan_block_kernel resets it each pass so graph replays stay correct.
__device__ int    g_hist[NCELLS];      // zero-initialized
__device__ int    g_offsets[NCELLS];   // exclusive prefix within 1024-chunk
__device__ int    g_blocksums[256];    // RAW chunk totals (scanned inline in scatter)
__device__ int    g_cell[B_MAX];
__device__ float4 g_pts[B_MAX];        // sorted payload: (x, y, z, bitcast(point id))

__global__ void hist_kernel(const float* __restrict__ x, int B) {
    int p = blockIdx.x * blockDim.x + threadIdx.x;
    if (p >= B) return;
    const float scale = (float)N_GRID / 2.0f;
    float rx = (x[p * 3 + 0] + 1.0f) * scale;
    float ry = (x[p * 3 + 1] + 1.0f) * scale;
    float rz = (x[p * 3 + 2] + 1.0f) * scale;
    int ix = min(max((int)floorf(rx), 0), N_GRID - 1);
    int iy = min(max((int)floorf(ry), 0), N_GRID - 1);
    int iz = min(max((int)floorf(rz), 0), N_GRID - 1);
    int cell = (ix * N_GRID + iy) * N_GRID + iz;   // lexicographic = memory order
    g_cell[p] = cell;
    atomicAdd(&g_hist[cell], 1);
}

// 256 blocks x 1024 threads: shuffle-based exclusive scan of each 1024-chunk
// into g_offsets, reset g_hist, emit RAW chunk total.
__global__ void __launch_bounds__(1024) scan_block_kernel() {
    __shared__ int wsum[32];
    int tid = threadIdx.x;
    int lane = tid & 31;
    int wid = tid >> 5;
    int i = blockIdx.x * 1024 + tid;

    int v = g_hist[i];
    int inc = v;
    #pragma unroll
    for (int off = 1; off < 32; off <<= 1) {
        int t = __shfl_up_sync(0xFFFFFFFF, inc, off);
        if (lane >= off) inc += t;
    }
    if (lane == 31) wsum[wid] = inc;
    __syncthreads();
    if (wid == 0) {
        int ws = wsum[lane];
        int winc = ws;
        #pragma unroll
        for (int off = 1; off < 32; off <<= 1) {
            int t = __shfl_up_sync(0xFFFFFFFF, winc, off);
            if (lane >= off) winc += t;
        }
        wsum[lane] = winc - ws;      // exclusive warp prefix
    }
    __syncthreads();
    int excl = inc - v + wsum[wid];
    g_offsets[i] = excl;
    g_hist[i] = 0;                   // ready for next replay
    if (tid == 1023) g_blocksums[blockIdx.x] = excl + v;  // raw chunk total
}

// 1024 blocks x 256 threads. Each block first scans the 256 raw chunk totals
// in smem (replaces the scan_top kernel), then scatters 256 points as float4
// payloads into sorted order.
__global__ void __launch_bounds__(256) scatter_kernel(const float* __restrict__ x, int B) {
    __shared__ int bs[256];
    __shared__ int wsum[8];
    int tid = threadIdx.x;
    int lane = tid & 31;
    int wid = tid >> 5;

    int raw = g_blocksums[tid];
    int inc = raw;
    #pragma unroll
    for (int off = 1; off < 32; off <<= 1) {
        int t = __shfl_up_sync(0xFFFFFFFF, inc, off);
        if (lane >= off) inc += t;
    }
    if (lane == 31) wsum[wid] = inc;
    __syncthreads();
    if (wid == 0 && lane < 8) {
        int ws = wsum[lane];
        int winc = ws;
        #pragma unroll
        for (int off = 1; off < 8; off <<= 1) {
            int t = __shfl_up_sync(0x000000FF, winc, off);
            if (lane >= off) winc += t;
        }
        wsum[lane] = winc - ws;      // exclusive warp prefix
    }
    __syncthreads();
    bs[tid] = inc - raw + wsum[wid]; // exclusive prefix of chunk totals
    __syncthreads();

    int p = blockIdx.x * 256 + tid;
    if (p >= B) return;
    int c = g_cell[p];
    int pos = atomicAdd(&g_offsets[c], 1) + bs[c >> 10];
    g_pts[pos] = make_float4(x[p * 3 + 0], x[p * 3 + 1], x[p * 3 + 2],
                             __int_as_float(p));
}

// warp-per-point trilinear gather; warps walk points in cell-sorted order.
// R6/R8-measured-best loop (interleaved load/FMA, 44 regs).
// 128-thread blocks: 11 blocks/SM at 44 regs -> 44 resident warps (vs 40).
__global__ void __launch_bounds__(128) trilerp_kernel(
    const float* __restrict__ grid_value,
    const float* __restrict__ grid_feature,
    float* __restrict__ out_val,
    float* __restrict__ out_feat,
    int B)
{
    int warp_id = (blockIdx.x * blockDim.x + threadIdx.x) >> 5;
    int lane = threadIdx.x & 31;
    if (warp_id >= B) return;

    float4 pt = __ldg(&g_pts[warp_id]);   // broadcast: coords + point id
    float px = pt.x, py = pt.y, pz = pt.z;
    int p = __float_as_int(pt.w);

    const float scale = (float)N_GRID / 2.0f;
    float rx = (px + 1.0f) * scale;
    float ry = (py + 1.0f) * scale;
    float rz = (pz + 1.0f) * scale;

    bool valid = (rx >= 0.0f) && (rx <= (float)N_GRID) &&
                 (ry >= 0.0f) && (ry <= (float)N_GRID) &&
                 (rz >= 0.0f) && (rz <= (float)N_GRID);

    int ix = min(max((int)floorf(rx), 0), N_GRID - 1);
    int iy = min(max((int)floorf(ry), 0), N_GRID - 1);
    int iz = min(max((int)floorf(rz), 0), N_GRID - 1);

    float tx = rx - (float)ix;
    float ty = ry - (float)iy;
    float tz = rz - (float)iz;

    int base = (ix * N1 + iy) * N1 + iz;

    float wx0 = 1.0f - tx, wx1 = tx;
    float wy0 = 1.0f - ty, wy1 = ty;
    float wz0 = 1.0f - tz, wz1 = tz;

    int   flat[8];
    float w[8];
    flat[0] = base;                      w[0] = wx0 * wy0 * wz0;
    flat[1] = base + 1;                  w[1] = wx0 * wy0 * wz1;
    flat[2] = base + N1;                 w[2] = wx0 * wy1 * wz0;
    flat[3] = base + N1 + 1;             w[3] = wx0 * wy1 * wz1;
    flat[4] = base + N1 * N1;            w[4] = wx1 * wy0 * wz0;
    flat[5] = base + N1 * N1 + 1;        w[5] = wx1 * wy0 * wz1;
    flat[6] = base + N1 * N1 + N1;       w[6] = wx1 * wy1 * wz0;
    flat[7] = base + N1 * N1 + N1 + 1;   w[7] = wx1 * wy1 * wz1;

    float4 acc0 = make_float4(0.f, 0.f, 0.f, 0.f);
    float4 acc1 = make_float4(0.f, 0.f, 0.f, 0.f);

    #pragma unroll
    for (int c = 0; c < 8; c++) {
        const float4* row = (const float4*)(grid_feature + (size_t)flat[c] * W_FEAT);
        float4 f0 = __ldg(&row[lane]);
        float4 f1 = __ldg(&row[lane + 32]);
        float wc = w[c];
        acc0.x += wc * f0.x; acc0.y += wc * f0.y;
        acc0.z += wc * f0.z; acc0.w += wc * f0.w;
        acc1.x += wc * f1.x; acc1.y += wc * f1.y;
        acc1.z += wc * f1.z; acc1.w += wc * f1.w;
    }

    if (!valid) {
        acc0 = make_float4(0.f, 0.f, 0.f, 0.f);
        acc1 = make_float4(0.f, 0.f, 0.f, 0.f);
    }

    float4* fo = (float4*)(out_feat + (size_t)p * W_FEAT);
    fo[lane]      = acc0;
    fo[lane + 32] = acc1;

    if (lane == 0) {
        float s = 0.0f;
        #pragma unroll
        for (int c = 0; c < 8; c++) s += w[c] * __ldg(&grid_value[flat[c]]);
        out_val[p] = valid ? s : 0.0f;
    }
}

extern "C" void kernel_launch(void* const* d_in, const int* in_sizes, int n_in,
                              void* d_out, int out_size) {
    const float* x            = (const float*)d_in[0];
    const float* grid_value   = (const float*)d_in[1];
    const float* grid_feature = (const float*)d_in[2];

    int B = in_sizes[0] / 3;

    float* out_val  = (float*)d_out;        // (B, 1)
    float* out_feat = out_val + B;          // (B, 256)

    // --- counting sort by full cell id (4 launches total incl. main) ---
    hist_kernel<<<(B + 255) / 256, 256>>>(x, B);
    scan_block_kernel<<<NCELLS / 1024, 1024>>>();
    scatter_kernel<<<(B + 255) / 256, 256>>>(x, B);

    // --- main gather: warp per point, sorted order, 128-thread blocks ---
    int warps_per_block = 4;                 // 128 threads
    int blocks = (B + warps_per_block - 1) / warps_per_block;
    trilerp_kernel<<<blocks, 128>>>(grid_value, grid_feature,
                                    out_val, out_feat, B);
}

// round 12
// speedup vs baseline: 1.4777x; 1.1249x over previous
#include <cuda_runtime.h>
#include <cuda_bf16.h>

#define N_GRID 64
#define N1 65
#define W_FEAT 256
#define NCELLS (N_GRID * N_GRID * N_GRID)   // 262144
#define B_MAX 262144

// Scratch (allocation-free rule: __device__ globals).
// g_hist must be zero at first use: static zero-init gives that, and
// scan_block_kernel resets it each pass so graph replays stay correct.
__device__ int    g_hist[NCELLS];      // zero-initialized
__device__ int    g_offsets[NCELLS];   // exclusive prefix within 1024-chunk
__device__ int    g_blocksums[256];    // RAW chunk totals (scanned inline in scatter)
__device__ int    g_cell[B_MAX];
__device__ float4 g_pts[B_MAX];        // sorted payload: (x, y, z, bitcast(point id))

__global__ void hist_kernel(const float* __restrict__ x, int B) {
    int p = blockIdx.x * blockDim.x + threadIdx.x;
    if (p >= B) return;
    const float scale = (float)N_GRID / 2.0f;
    float rx = (x[p * 3 + 0] + 1.0f) * scale;
    float ry = (x[p * 3 + 1] + 1.0f) * scale;
    float rz = (x[p * 3 + 2] + 1.0f) * scale;
    int ix = min(max((int)floorf(rx), 0), N_GRID - 1);
    int iy = min(max((int)floorf(ry), 0), N_GRID - 1);
    int iz = min(max((int)floorf(rz), 0), N_GRID - 1);
    int cell = (ix * N_GRID + iy) * N_GRID + iz;   // lexicographic = memory order
    g_cell[p] = cell;
    atomicAdd(&g_hist[cell], 1);
}

// 256 blocks x 1024 threads: shuffle-based exclusive scan of each 1024-chunk
// into g_offsets, reset g_hist, emit RAW chunk total.
__global__ void __launch_bounds__(1024) scan_block_kernel() {
    __shared__ int wsum[32];
    int tid = threadIdx.x;
    int lane = tid & 31;
    int wid = tid >> 5;
    int i = blockIdx.x * 1024 + tid;

    int v = g_hist[i];
    int inc = v;
    #pragma unroll
    for (int off = 1; off < 32; off <<= 1) {
        int t = __shfl_up_sync(0xFFFFFFFF, inc, off);
        if (lane >= off) inc += t;
    }
    if (lane == 31) wsum[wid] = inc;
    __syncthreads();
    if (wid == 0) {
        int ws = wsum[lane];
        int winc = ws;
        #pragma unroll
        for (int off = 1; off < 32; off <<= 1) {
            int t = __shfl_up_sync(0xFFFFFFFF, winc, off);
            if (lane >= off) winc += t;
        }
        wsum[lane] = winc - ws;      // exclusive warp prefix
    }
    __syncthreads();
    int excl = inc - v + wsum[wid];
    g_offsets[i] = excl;
    g_hist[i] = 0;                   // ready for next replay
    if (tid == 1023) g_blocksums[blockIdx.x] = excl + v;  // raw chunk total
}

// 1024 blocks x 256 threads. Each block first scans the 256 raw chunk totals
// in smem (replaces the scan_top kernel), then scatters 256 points as float4
// payloads into sorted order.
__global__ void __launch_bounds__(256) scatter_kernel(const float* __restrict__ x, int B) {
    __shared__ int bs[256];
    __shared__ int wsum[8];
    int tid = threadIdx.x;
    int lane = tid & 31;
    int wid = tid >> 5;

    int raw = g_blocksums[tid];
    int inc = raw;
    #pragma unroll
    for (int off = 1; off < 32; off <<= 1) {
        int t = __shfl_up_sync(0xFFFFFFFF, inc, off);
        if (lane >= off) inc += t;
    }
    if (lane == 31) wsum[wid] = inc;
    __syncthreads();
    if (wid == 0 && lane < 8) {
        int ws = wsum[lane];
        int winc = ws;
        #pragma unroll
        for (int off = 1; off < 8; off <<= 1) {
            int t = __shfl_up_sync(0x000000FF, winc, off);
            if (lane >= off) winc += t;
        }
        wsum[lane] = winc - ws;      // exclusive warp prefix
    }
    __syncthreads();
    bs[tid] = inc - raw + wsum[wid]; // exclusive prefix of chunk totals
    __syncthreads();

    int p = blockIdx.x * 256 + tid;
    if (p >= B) return;
    int c = g_cell[p];
    int pos = atomicAdd(&g_offsets[c], 1) + bs[c >> 10];
    g_pts[pos] = make_float4(x[p * 3 + 0], x[p * 3 + 1], x[p * 3 + 2],
                             __int_as_float(p));
}

// Thread-per-point scalar grid_value interpolation, in sorted order.
// Consecutive threads hit consecutive cells -> corner loads coalesce;
// grid_value (1MB) is L2/L1-resident.
__global__ void __launch_bounds__(256) gridval_kernel(
    const float* __restrict__ grid_value,
    float* __restrict__ out_val,
    int B)
{
    int i = blockIdx.x * blockDim.x + threadIdx.x;
    if (i >= B) return;

    float4 pt = __ldg(&g_pts[i]);
    int p = __float_as_int(pt.w);

    const float scale = (float)N_GRID / 2.0f;
    float rx = (pt.x + 1.0f) * scale;
    float ry = (pt.y + 1.0f) * scale;
    float rz = (pt.z + 1.0f) * scale;

    bool valid = (rx >= 0.0f) && (rx <= (float)N_GRID) &&
                 (ry >= 0.0f) && (ry <= (float)N_GRID) &&
                 (rz >= 0.0f) && (rz <= (float)N_GRID);

    int ix = min(max((int)floorf(rx), 0), N_GRID - 1);
    int iy = min(max((int)floorf(ry), 0), N_GRID - 1);
    int iz = min(max((int)floorf(rz), 0), N_GRID - 1);

    float tx = rx - (float)ix;
    float ty = ry - (float)iy;
    float tz = rz - (float)iz;

    int base = (ix * N1 + iy) * N1 + iz;

    float wx0 = 1.0f - tx, wx1 = tx;
    float wy0 = 1.0f - ty, wy1 = ty;
    float wz0 = 1.0f - tz, wz1 = tz;

    float v000 = __ldg(&grid_value[base]);
    float v001 = __ldg(&grid_value[base + 1]);
    float v010 = __ldg(&grid_value[base + N1]);
    float v011 = __ldg(&grid_value[base + N1 + 1]);
    float v100 = __ldg(&grid_value[base + N1 * N1]);
    float v101 = __ldg(&grid_value[base + N1 * N1 + 1]);
    float v110 = __ldg(&grid_value[base + N1 * N1 + N1]);
    float v111 = __ldg(&grid_value[base + N1 * N1 + N1 + 1]);

    float s = wx0 * wy0 * wz0 * v000 + wx0 * wy0 * wz1 * v001
            + wx0 * wy1 * wz0 * v010 + wx0 * wy1 * wz1 * v011
            + wx1 * wy0 * wz0 * v100 + wx1 * wy0 * wz1 * v101
            + wx1 * wy1 * wz0 * v110 + wx1 * wy1 * wz1 * v111;

    out_val[p] = valid ? s : 0.0f;
}

// warp-per-point trilinear feature gather; warps walk points in sorted order.
// R6/R8-measured-best loop (interleaved load/FMA). (128, 12): 48 warps/SM.
__global__ void __launch_bounds__(128, 12) trilerp_kernel(
    const float* __restrict__ grid_feature,
    float* __restrict__ out_feat,
    int B)
{
    int warp_id = (blockIdx.x * blockDim.x + threadIdx.x) >> 5;
    int lane = threadIdx.x & 31;
    if (warp_id >= B) return;

    float4 pt = __ldg(&g_pts[warp_id]);   // broadcast: coords + point id
    int p = __float_as_int(pt.w);

    const float scale = (float)N_GRID / 2.0f;
    float rx = (pt.x + 1.0f) * scale;
    float ry = (pt.y + 1.0f) * scale;
    float rz = (pt.z + 1.0f) * scale;

    bool valid = (rx >= 0.0f) && (rx <= (float)N_GRID) &&
                 (ry >= 0.0f) && (ry <= (float)N_GRID) &&
                 (rz >= 0.0f) && (rz <= (float)N_GRID);

    int ix = min(max((int)floorf(rx), 0), N_GRID - 1);
    int iy = min(max((int)floorf(ry), 0), N_GRID - 1);
    int iz = min(max((int)floorf(rz), 0), N_GRID - 1);

    float tx = rx - (float)ix;
    float ty = ry - (float)iy;
    float tz = rz - (float)iz;

    int base = (ix * N1 + iy) * N1 + iz;

    float wx0 = 1.0f - tx, wx1 = tx;
    float wy0 = 1.0f - ty, wy1 = ty;
    float wz0 = 1.0f - tz, wz1 = tz;

    int   flat[8];
    float w[8];
    flat[0] = base;                      w[0] = wx0 * wy0 * wz0;
    flat[1] = base + 1;                  w[1] = wx0 * wy0 * wz1;
    flat[2] = base + N1;                 w[2] = wx0 * wy1 * wz0;
    flat[3] = base + N1 + 1;             w[3] = wx0 * wy1 * wz1;
    flat[4] = base + N1 * N1;            w[4] = wx1 * wy0 * wz0;
    flat[5] = base + N1 * N1 + 1;        w[5] = wx1 * wy0 * wz1;
    flat[6] = base + N1 * N1 + N1;       w[6] = wx1 * wy1 * wz0;
    flat[7] = base + N1 * N1 + N1 + 1;   w[7] = wx1 * wy1 * wz1;

    float4 acc0 = make_float4(0.f, 0.f, 0.f, 0.f);
    float4 acc1 = make_float4(0.f, 0.f, 0.f, 0.f);

    #pragma unroll
    for (int c = 0; c < 8; c++) {
        const float4* row = (const float4*)(grid_feature + (size_t)flat[c] * W_FEAT);
        float4 f0 = __ldg(&row[lane]);
        float4 f1 = __ldg(&row[lane + 32]);
        float wc = w[c];
        acc0.x += wc * f0.x; acc0.y += wc * f0.y;
        acc0.z += wc * f0.z; acc0.w += wc * f0.w;
        acc1.x += wc * f1.x; acc1.y += wc * f1.y;
        acc1.z += wc * f1.z; acc1.w += wc * f1.w;
    }

    if (!valid) {
        acc0 = make_float4(0.f, 0.f, 0.f, 0.f);
        acc1 = make_float4(0.f, 0.f, 0.f, 0.f);
    }

    float4* fo = (float4*)(out_feat + (size_t)p * W_FEAT);
    fo[lane]      = acc0;
    fo[lane + 32] = acc1;
}

extern "C" void kernel_launch(void* const* d_in, const int* in_sizes, int n_in,
                              void* d_out, int out_size) {
    const float* x            = (const float*)d_in[0];
    const float* grid_value   = (const float*)d_in[1];
    const float* grid_feature = (const float*)d_in[2];

    int B = in_sizes[0] / 3;

    float* out_val  = (float*)d_out;        // (B, 1)
    float* out_feat = out_val + B;          // (B, 256)

    // --- counting sort by full cell id ---
    hist_kernel<<<(B + 255) / 256, 256>>>(x, B);
    scan_block_kernel<<<NCELLS / 1024, 1024>>>();
    scatter_kernel<<<(B + 255) / 256, 256>>>(x, B);

    // --- scalar grid_value path: thread per point, sorted (coalesced) ---
    gridval_kernel<<<(B + 255) / 256, 256>>>(grid_value, out_val, B);

    // --- feature gather: warp per point, sorted order ---
    int warps_per_block = 4;                 // 128 threads
    int blocks = (B + warps_per_block - 1) / warps_per_block;
    trilerp_kernel<<<blocks, 128>>>(grid_feature, out_feat, B);
}

// round 14
// speedup vs baseline: 1.5275x; 1.0337x over previous
#include <cuda_runtime.h>
#include <cuda_bf16.h>

#define N_GRID 64
#define N1 65
#define W_FEAT 256
#define NCELLS (N_GRID * N_GRID * N_GRID)   // 262144
#define B_MAX 262144

// Scratch (allocation-free rule: __device__ globals).
// g_hist must be zero at first use: static zero-init gives that, and
// scan_block_kernel resets it each pass so graph replays stay correct.
__device__ int    g_hist[NCELLS];      // zero-initialized
__device__ int    g_offsets[NCELLS];   // exclusive prefix within 1024-chunk
__device__ int    g_blocksums[256];    // RAW chunk totals (scanned inline in scatter)
__device__ int    g_cell[B_MAX];
__device__ float4 g_pts[B_MAX];        // sorted payload: (x, y, z, bitcast(point id))

__global__ void hist_kernel(const float* __restrict__ x, int B) {
    int p = blockIdx.x * blockDim.x + threadIdx.x;
    if (p >= B) return;
    const float scale = (float)N_GRID / 2.0f;
    float rx = (x[p * 3 + 0] + 1.0f) * scale;
    float ry = (x[p * 3 + 1] + 1.0f) * scale;
    float rz = (x[p * 3 + 2] + 1.0f) * scale;
    int ix = min(max((int)floorf(rx), 0), N_GRID - 1);
    int iy = min(max((int)floorf(ry), 0), N_GRID - 1);
    int iz = min(max((int)floorf(rz), 0), N_GRID - 1);
    int cell = (ix * N_GRID + iy) * N_GRID + iz;   // lexicographic = memory order
    g_cell[p] = cell;
    atomicAdd(&g_hist[cell], 1);
}

// 256 blocks x 1024 threads: shuffle-based exclusive scan of each 1024-chunk
// into g_offsets, reset g_hist, emit RAW chunk total.
__global__ void __launch_bounds__(1024) scan_block_kernel() {
    __shared__ int wsum[32];
    int tid = threadIdx.x;
    int lane = tid & 31;
    int wid = tid >> 5;
    int i = blockIdx.x * 1024 + tid;

    int v = g_hist[i];
    int inc = v;
    #pragma unroll
    for (int off = 1; off < 32; off <<= 1) {
        int t = __shfl_up_sync(0xFFFFFFFF, inc, off);
        if (lane >= off) inc += t;
    }
    if (lane == 31) wsum[wid] = inc;
    __syncthreads();
    if (wid == 0) {
        int ws = wsum[lane];
        int winc = ws;
        #pragma unroll
        for (int off = 1; off < 32; off <<= 1) {
            int t = __shfl_up_sync(0xFFFFFFFF, winc, off);
            if (lane >= off) winc += t;
        }
        wsum[lane] = winc - ws;      // exclusive warp prefix
    }
    __syncthreads();
    int excl = inc - v + wsum[wid];
    g_offsets[i] = excl;
    g_hist[i] = 0;                   // ready for next replay
    if (tid == 1023) g_blocksums[blockIdx.x] = excl + v;  // raw chunk total
}

// 1024 blocks x 256 threads. Each block first scans the 256 raw chunk totals
// in smem, then scatters 256 points as float4 payloads into sorted order.
__global__ void __launch_bounds__(256) scatter_kernel(const float* __restrict__ x, int B) {
    __shared__ int bs[256];
    __shared__ int wsum[8];
    int tid = threadIdx.x;
    int lane = tid & 31;
    int wid = tid >> 5;

    int raw = g_blocksums[tid];
    int inc = raw;
    #pragma unroll
    for (int off = 1; off < 32; off <<= 1) {
        int t = __shfl_up_sync(0xFFFFFFFF, inc, off);
        if (lane >= off) inc += t;
    }
    if (lane == 31) wsum[wid] = inc;
    __syncthreads();
    if (wid == 0 && lane < 8) {
        int ws = wsum[lane];
        int winc = ws;
        #pragma unroll
        for (int off = 1; off < 8; off <<= 1) {
            int t = __shfl_up_sync(0x000000FF, winc, off);
            if (lane >= off) winc += t;
        }
        wsum[lane] = winc - ws;      // exclusive warp prefix
    }
    __syncthreads();
    bs[tid] = inc - raw + wsum[wid]; // exclusive prefix of chunk totals
    __syncthreads();

    int p = blockIdx.x * 256 + tid;
    if (p >= B) return;
    int c = g_cell[p];
    int pos = atomicAdd(&g_offsets[c], 1) + bs[c >> 10];
    g_pts[pos] = make_float4(x[p * 3 + 0], x[p * 3 + 1], x[p * 3 + 2],
                             __int_as_float(p));
}

// Thread-per-point scalar grid_value interpolation, in sorted order.
__global__ void __launch_bounds__(256) gridval_kernel(
    const float* __restrict__ grid_value,
    float* __restrict__ out_val,
    int B)
{
    int i = blockIdx.x * blockDim.x + threadIdx.x;
    if (i >= B) return;

    float4 pt = __ldg(&g_pts[i]);
    int p = __float_as_int(pt.w);

    const float scale = (float)N_GRID / 2.0f;
    float rx = (pt.x + 1.0f) * scale;
    float ry = (pt.y + 1.0f) * scale;
    float rz = (pt.z + 1.0f) * scale;

    bool valid = (rx >= 0.0f) && (rx <= (float)N_GRID) &&
                 (ry >= 0.0f) && (ry <= (float)N_GRID) &&
                 (rz >= 0.0f) && (rz <= (float)N_GRID);

    int ix = min(max((int)floorf(rx), 0), N_GRID - 1);
    int iy = min(max((int)floorf(ry), 0), N_GRID - 1);
    int iz = min(max((int)floorf(rz), 0), N_GRID - 1);

    float tx = rx - (float)ix;
    float ty = ry - (float)iy;
    float tz = rz - (float)iz;

    int base = (ix * N1 + iy) * N1 + iz;

    float wx0 = 1.0f - tx, wx1 = tx;
    float wy0 = 1.0f - ty, wy1 = ty;
    float wz0 = 1.0f - tz, wz1 = tz;

    float v000 = __ldg(&grid_value[base]);
    float v001 = __ldg(&grid_value[base + 1]);
    float v010 = __ldg(&grid_value[base + N1]);
    float v011 = __ldg(&grid_value[base + N1 + 1]);
    float v100 = __ldg(&grid_value[base + N1 * N1]);
    float v101 = __ldg(&grid_value[base + N1 * N1 + 1]);
    float v110 = __ldg(&grid_value[base + N1 * N1 + N1]);
    float v111 = __ldg(&grid_value[base + N1 * N1 + N1 + 1]);

    float s = wx0 * wy0 * wz0 * v000 + wx0 * wy0 * wz1 * v001
            + wx0 * wy1 * wz0 * v010 + wx0 * wy1 * wz1 * v011
            + wx1 * wy0 * wz0 * v100 + wx1 * wy0 * wz1 * v101
            + wx1 * wy1 * wz0 * v110 + wx1 * wy1 * wz1 * v111;

    out_val[p] = valid ? s : 0.0f;
}

// Per-point setup: weights, base cell, validity, output id.
struct PointW {
    int   base;
    int   p;
    bool  valid;
    float w[8];
};

__device__ __forceinline__ PointW make_pointw(float4 pt) {
    PointW r;
    r.p = __float_as_int(pt.w);
    const float scale = (float)N_GRID / 2.0f;
    float rx = (pt.x + 1.0f) * scale;
    float ry = (pt.y + 1.0f) * scale;
    float rz = (pt.z + 1.0f) * scale;
    r.valid = (rx >= 0.0f) && (rx <= (float)N_GRID) &&
              (ry >= 0.0f) && (ry <= (float)N_GRID) &&
              (rz >= 0.0f) && (rz <= (float)N_GRID);
    int ix = min(max((int)floorf(rx), 0), N_GRID - 1);
    int iy = min(max((int)floorf(ry), 0), N_GRID - 1);
    int iz = min(max((int)floorf(rz), 0), N_GRID - 1);
    float tx = rx - (float)ix, ty = ry - (float)iy, tz = rz - (float)iz;
    r.base = (ix * N1 + iy) * N1 + iz;
    float wx0 = 1.0f - tx, wx1 = tx;
    float wy0 = 1.0f - ty, wy1 = ty;
    float wz0 = 1.0f - tz, wz1 = tz;
    r.w[0] = wx0 * wy0 * wz0;
    r.w[1] = wx0 * wy0 * wz1;
    r.w[2] = wx0 * wy1 * wz0;
    r.w[3] = wx0 * wy1 * wz1;
    r.w[4] = wx1 * wy0 * wz0;
    r.w[5] = wx1 * wy0 * wz1;
    r.w[6] = wx1 * wy1 * wz0;
    r.w[7] = wx1 * wy1 * wz1;
    return r;
}

__device__ __forceinline__ void gather_one(
    const float* __restrict__ grid_feature, const PointW& q, int lane,
    float* __restrict__ out_feat)
{
    float4 acc0 = make_float4(0.f, 0.f, 0.f, 0.f);
    float4 acc1 = make_float4(0.f, 0.f, 0.f, 0.f);
    #pragma unroll
    for (int c = 0; c < 8; c++) {
        int off = (((c >> 2) & 1) * (N1 * N1) + ((c >> 1) & 1) * N1 + (c & 1));
        const float4* row = (const float4*)(grid_feature + (size_t)(q.base + off) * W_FEAT);
        float4 f0 = __ldg(&row[lane]);
        float4 f1 = __ldg(&row[lane + 32]);
        float wc = q.w[c];
        acc0.x += wc * f0.x; acc0.y += wc * f0.y;
        acc0.z += wc * f0.z; acc0.w += wc * f0.w;
        acc1.x += wc * f1.x; acc1.y += wc * f1.y;
        acc1.z += wc * f1.z; acc1.w += wc * f1.w;
    }
    if (!q.valid) {
        acc0 = make_float4(0.f, 0.f, 0.f, 0.f);
        acc1 = make_float4(0.f, 0.f, 0.f, 0.f);
    }
    float4* fo = (float4*)(out_feat + (size_t)q.p * W_FEAT);
    fo[lane]      = acc0;
    fo[lane + 32] = acc1;
}

// Warp per PAIR of consecutive sorted points. Same cell -> one load pass
// feeds both accumulator sets (saves ~37% of pairs' loads); else two passes.
// Branch is warp-uniform (cell ids identical across lanes).
__global__ void __launch_bounds__(128) trilerp_kernel(
    const float* __restrict__ grid_feature,
    float* __restrict__ out_feat,
    int B)
{
    int pw = (blockIdx.x * blockDim.x + threadIdx.x) >> 5;  // pair index
    int lane = threadIdx.x & 31;
    int i0 = pw * 2;
    if (i0 >= B) return;
    bool haveB = (i0 + 1 < B);

    float4 ptA = __ldg(&g_pts[i0]);
    float4 ptB = haveB ? __ldg(&g_pts[i0 + 1]) : ptA;

    PointW A = make_pointw(ptA);
    PointW Bq = make_pointw(ptB);

    if (haveB && Bq.base == A.base) {
        // shared loads, dual accumulation (per-point FMA order preserved)
        float4 a0 = make_float4(0.f, 0.f, 0.f, 0.f);
        float4 a1 = make_float4(0.f, 0.f, 0.f, 0.f);
        float4 b0 = make_float4(0.f, 0.f, 0.f, 0.f);
        float4 b1 = make_float4(0.f, 0.f, 0.f, 0.f);
        #pragma unroll
        for (int c = 0; c < 8; c++) {
            int off = (((c >> 2) & 1) * (N1 * N1) + ((c >> 1) & 1) * N1 + (c & 1));
            const float4* row = (const float4*)(grid_feature + (size_t)(A.base + off) * W_FEAT);
            float4 f0 = __ldg(&row[lane]);
            float4 f1 = __ldg(&row[lane + 32]);
            float wa = A.w[c], wb = Bq.w[c];
            a0.x += wa * f0.x; a0.y += wa * f0.y; a0.z += wa * f0.z; a0.w += wa * f0.w;
            a1.x += wa * f1.x; a1.y += wa * f1.y; a1.z += wa * f1.z; a1.w += wa * f1.w;
            b0.x += wb * f0.x; b0.y += wb * f0.y; b0.z += wb * f0.z; b0.w += wb * f0.w;
            b1.x += wb * f1.x; b1.y += wb * f1.y; b1.z += wb * f1.z; b1.w += wb * f1.w;
        }
        if (!A.valid)  { a0 = make_float4(0,0,0,0); a1 = make_float4(0,0,0,0); }
        if (!Bq.valid) { b0 = make_float4(0,0,0,0); b1 = make_float4(0,0,0,0); }
        float4* foA = (float4*)(out_feat + (size_t)A.p * W_FEAT);
        foA[lane]      = a0;
        foA[lane + 32] = a1;
        float4* foB = (float4*)(out_feat + (size_t)Bq.p * W_FEAT);
        foB[lane]      = b0;
        foB[lane + 32] = b1;
    } else {
        gather_one(grid_feature, A, lane, out_feat);
        if (haveB) gather_one(grid_feature, Bq, lane, out_feat);
    }
}

extern "C" void kernel_launch(void* const* d_in, const int* in_sizes, int n_in,
                              void* d_out, int out_size) {
    const float* x            = (const float*)d_in[0];
    const float* grid_value   = (const float*)d_in[1];
    const float* grid_feature = (const float*)d_in[2];

    int B = in_sizes[0] / 3;

    float* out_val  = (float*)d_out;        // (B, 1)
    float* out_feat = out_val + B;          // (B, 256)

    // --- counting sort by full cell id ---
    hist_kernel<<<(B + 255) / 256, 256>>>(x, B);
    scan_block_kernel<<<NCELLS / 1024, 1024>>>();
    scatter_kernel<<<(B + 255) / 256, 256>>>(x, B);

    // --- scalar grid_value path: thread per point, sorted (coalesced) ---
    gridval_kernel<<<(B + 255) / 256, 256>>>(grid_value, out_val, B);

    // --- feature gather: warp per sorted PAIR ---
    int pairs = (B + 1) / 2;
    int warps_per_block = 4;                 // 128 threads
    int blocks = (pairs + warps_per_block - 1) / warps_per_block;
    trilerp_kernel<<<blocks, 128>>>(grid_feature, out_feat, B);
}